// round 2
// baseline (speedup 1.0000x reference)
#include <cuda_runtime.h>
#include <cuda_bf16.h>
#include <cstdint>

// ============================================================================
// AWAttention on B200, compiled for baseline sm_100 (no 'a' features).
//   Q = A@Wq^T + bq ; K = X@Wk^T + bk ; S = Q@K^T ; P = softmax(S) ; O = P@X
// All GEMMs share one kernel: C[M,N] = A[M,K] @ B[N,K]^T (+bias over N),
// A,B given as split bf16 (hi,lo); accumulate hh + hl + lh in fp32 registers
// via mma.sync.m16n8k16 (ldmatrix + cp.async pipeline). No tcgen05 anywhere.
// ============================================================================

#define SWZ(x) ((x) ^ (((x) >> 3) & 0x70))

__device__ __forceinline__ uint32_t smem_u32(const void* p) {
    uint32_t a;
    asm("{ .reg .u64 t; cvta.to.shared.u64 t, %1; cvt.u32.u64 %0, t; }" : "=r"(a) : "l"(p));
    return a;
}

#define CP_ASYNC16(sm, gm) \
    asm volatile("cp.async.cg.shared.global [%0], [%1], 16;" :: "r"(sm), "l"(gm))
#define CP_COMMIT() asm volatile("cp.async.commit_group;" ::: "memory")
#define CP_WAIT1()  asm volatile("cp.async.wait_group 1;" ::: "memory")

__device__ __forceinline__ void ldmx4(uint32_t r[4], uint32_t addr) {
    asm volatile("ldmatrix.sync.aligned.m8n8.x4.shared.b16 {%0,%1,%2,%3}, [%4];"
                 : "=r"(r[0]), "=r"(r[1]), "=r"(r[2]), "=r"(r[3]) : "r"(addr));
}

__device__ __forceinline__ void mma16816(float c[4], const uint32_t a[4],
                                         const uint32_t b0, const uint32_t b1) {
    asm volatile(
        "mma.sync.aligned.m16n8k16.row.col.f32.bf16.bf16.f32 "
        "{%0,%1,%2,%3}, {%4,%5,%6,%7}, {%8,%9}, {%0,%1,%2,%3};"
        : "+f"(c[0]), "+f"(c[1]), "+f"(c[2]), "+f"(c[3])
        : "r"(a[0]), "r"(a[1]), "r"(a[2]), "r"(a[3]), "r"(b0), "r"(b1));
}

static constexpr int TILE_BYTES  = 128 * 128;         // 128 rows x 128B (64 bf16)
static constexpr int STAGE_BYTES = 4 * TILE_BYTES;    // Ahi, Alo, Bhi, Blo
static constexpr int STAGES      = 3;
static constexpr int GEMM_SMEM   = STAGES * STAGE_BYTES;  // 196608

// Load one K-chunk (64 elems) of the 4 tiles into a stage via cp.async.
__device__ __forceinline__ void load_chunk(
    uint32_t stage, const __nv_bfloat16* __restrict__ Ahi,
    const __nv_bfloat16* __restrict__ Alo, const __nv_bfloat16* __restrict__ Bhi,
    const __nv_bfloat16* __restrict__ Blo, int m0, int n0, int kc, int K, int tid)
{
    const char* pAh = (const char*)Ahi;
    const char* pAl = (const char*)Alo;
    const char* pBh = (const char*)Bhi;
    const char* pBl = (const char*)Blo;
#pragma unroll
    for (int i = 0; i < 4; ++i) {
        int ch  = tid + i * 256;     // 0..1023
        int row = ch >> 3;
        int c16 = ch & 7;
        uint32_t soff = SWZ((uint32_t)(row * 128 + c16 * 16));
        size_t ga = ((size_t)(m0 + row) * K + (size_t)kc * 64) * 2 + (size_t)c16 * 16;
        size_t gb = ((size_t)(n0 + row) * K + (size_t)kc * 64) * 2 + (size_t)c16 * 16;
        CP_ASYNC16(stage + 0 * TILE_BYTES + soff, pAh + ga);
        CP_ASYNC16(stage + 1 * TILE_BYTES + soff, pAl + ga);
        CP_ASYNC16(stage + 2 * TILE_BYTES + soff, pBh + gb);
        CP_ASYNC16(stage + 3 * TILE_BYTES + soff, pBl + gb);
    }
}

__global__ void __launch_bounds__(256, 1) gemm_split_kernel(
    const __nv_bfloat16* __restrict__ Ahi, const __nv_bfloat16* __restrict__ Alo,
    const __nv_bfloat16* __restrict__ Bhi, const __nv_bfloat16* __restrict__ Blo,
    float* __restrict__ C, int M, int N, int K, const float* __restrict__ bias)
{
    extern __shared__ __align__(1024) unsigned char smem[];
    uint32_t sbase = smem_u32(smem);
    int tid = threadIdx.x, wid = tid >> 5, lane = tid & 31;
    int warp_m = wid & 1;   // 2 warps over M -> 64 rows each
    int warp_n = wid >> 1;  // 4 warps over N -> 32 cols each
    int m0 = blockIdx.y * 128, n0 = blockIdx.x * 128;

    float acc[4][4][4];  // [mtile][ntile][frag]
#pragma unroll
    for (int i = 0; i < 4; ++i)
#pragma unroll
        for (int j = 0; j < 4; ++j)
#pragma unroll
            for (int e = 0; e < 4; ++e) acc[i][j][e] = 0.0f;

    const int nch = K >> 6;

    // Prefetch STAGES-1 chunks
#pragma unroll
    for (int s = 0; s < STAGES - 1; ++s) {
        load_chunk(sbase + s * STAGE_BYTES, Ahi, Alo, Bhi, Blo, m0, n0, s, K, tid);
        CP_COMMIT();
    }

    // Per-lane ldmatrix base offsets (within a tile), before swizzle.
    // A: row = warp_m*64 + i*16 + (lane%16), colbyte = ks*32 + (lane/16)*16
    const int a_rowbase = warp_m * 64 + (lane & 15);
    const int a_colb    = (lane >> 4) * 16;
    // B: row = warp_n*32 + jb*16 + (lane%8) + ((lane>>3)&1)*8, colbyte same form
    const int b_rowbase = warp_n * 32 + (lane & 7) + ((lane >> 3) & 1) * 8;
    const int b_colb    = (lane >> 4) * 16;

    for (int c = 0; c < nch; ++c) {
        CP_WAIT1();
        __syncthreads();

        int nextc = c + STAGES - 1;
        if (nextc < nch) {
            load_chunk(sbase + (uint32_t)(nextc % STAGES) * STAGE_BYTES,
                       Ahi, Alo, Bhi, Blo, m0, n0, nextc, K, tid);
        }
        CP_COMMIT();

        uint32_t st = sbase + (uint32_t)(c % STAGES) * STAGE_BYTES;
        uint32_t tAh = st + 0 * TILE_BYTES;
        uint32_t tAl = st + 1 * TILE_BYTES;
        uint32_t tBh = st + 2 * TILE_BYTES;
        uint32_t tBl = st + 3 * TILE_BYTES;

#pragma unroll
        for (int ks = 0; ks < 4; ++ks) {
            uint32_t ah[4][4], al[4][4];
#pragma unroll
            for (int i = 0; i < 4; ++i) {
                uint32_t off = SWZ((uint32_t)((a_rowbase + i * 16) * 128 + ks * 32 + a_colb));
                ldmx4(ah[i], tAh + off);
                ldmx4(al[i], tAl + off);
            }
            uint32_t bh[4][2], bl[4][2];
#pragma unroll
            for (int jb = 0; jb < 2; ++jb) {
                uint32_t off = SWZ((uint32_t)((b_rowbase + jb * 16) * 128 + ks * 32 + b_colb));
                uint32_t r[4];
                ldmx4(r, tBh + off);
                bh[jb * 2 + 0][0] = r[0]; bh[jb * 2 + 0][1] = r[2];
                bh[jb * 2 + 1][0] = r[1]; bh[jb * 2 + 1][1] = r[3];
                ldmx4(r, tBl + off);
                bl[jb * 2 + 0][0] = r[0]; bl[jb * 2 + 0][1] = r[2];
                bl[jb * 2 + 1][0] = r[1]; bl[jb * 2 + 1][1] = r[3];
            }
#pragma unroll
            for (int i = 0; i < 4; ++i)
#pragma unroll
                for (int j = 0; j < 4; ++j) {
                    mma16816(acc[i][j], ah[i], bh[j][0], bh[j][1]);  // hi*hi
                    mma16816(acc[i][j], ah[i], bl[j][0], bl[j][1]);  // hi*lo
                    mma16816(acc[i][j], al[i], bh[j][0], bh[j][1]);  // lo*hi
                }
        }
        __syncthreads();
    }

    // Epilogue: direct register -> gmem float2 stores (+bias).
    int g = lane >> 2, t = lane & 3;
#pragma unroll
    for (int i = 0; i < 4; ++i) {
        int r0 = m0 + warp_m * 64 + i * 16 + g;
#pragma unroll
        for (int j = 0; j < 4; ++j) {
            int col = n0 + warp_n * 32 + j * 8 + t * 2;
            float b0 = 0.0f, b1 = 0.0f;
            if (bias) { b0 = __ldg(bias + col); b1 = __ldg(bias + col + 1); }
            float2 v0 = make_float2(acc[i][j][0] + b0, acc[i][j][1] + b1);
            float2 v1 = make_float2(acc[i][j][2] + b0, acc[i][j][3] + b1);
            *(float2*)(C + (size_t)r0 * N + col)       = v0;
            *(float2*)(C + (size_t)(r0 + 8) * N + col) = v1;
        }
    }
}

// ---------------------------------------------------------------------------
// fp32 -> (bf16 hi, bf16 lo) split
// ---------------------------------------------------------------------------
__global__ void split_kernel(const float* __restrict__ in,
                             __nv_bfloat16* __restrict__ hi,
                             __nv_bfloat16* __restrict__ lo, long long n)
{
    long long i = (long long)blockIdx.x * blockDim.x + threadIdx.x;
    long long stride = (long long)gridDim.x * blockDim.x;
    for (; i < n; i += stride) {
        float x = in[i];
        __nv_bfloat16 h = __float2bfloat16(x);
        hi[i] = h;
        lo[i] = __float2bfloat16(x - __bfloat162float(h));
    }
}

// ---------------------------------------------------------------------------
// Row softmax (N<=8192) writing split-bf16 probabilities
// ---------------------------------------------------------------------------
__global__ void __launch_bounds__(256) softmax_split_kernel(
    const float* __restrict__ S, __nv_bfloat16* __restrict__ Phi,
    __nv_bfloat16* __restrict__ Plo, int N)
{
    __shared__ float buf[8192];
    __shared__ float red[8];
    int row = blockIdx.x, tid = threadIdx.x;
    const float* s = S + (long long)row * N;

    float mx = -3.0e38f;
    for (int i = tid; i < N; i += 256) mx = fmaxf(mx, s[i]);
#pragma unroll
    for (int o = 16; o; o >>= 1) mx = fmaxf(mx, __shfl_xor_sync(0xFFFFFFFFu, mx, o));
    if ((tid & 31) == 0) red[tid >> 5] = mx;
    __syncthreads();
    mx = red[0];
#pragma unroll
    for (int w = 1; w < 8; ++w) mx = fmaxf(mx, red[w]);

    float sum = 0.0f;
    for (int i = tid; i < N; i += 256) {
        float e = __expf(s[i] - mx);
        buf[i] = e;
        sum += e;
    }
#pragma unroll
    for (int o = 16; o; o >>= 1) sum += __shfl_xor_sync(0xFFFFFFFFu, sum, o);
    __syncthreads();
    if ((tid & 31) == 0) red[tid >> 5] = sum;
    __syncthreads();
    sum = 0.0f;
#pragma unroll
    for (int w = 0; w < 8; ++w) sum += red[w];
    float inv = 1.0f / sum;

    for (int i = tid; i < N; i += 256) {
        float v = buf[i] * inv;
        __nv_bfloat16 h = __float2bfloat16(v);
        Phi[(long long)row * N + i] = h;
        Plo[(long long)row * N + i] = __float2bfloat16(v - __bfloat162float(h));
    }
}

// ---------------------------------------------------------------------------
// Transpose fp32 [R,C] -> split-bf16 [C,R]
// ---------------------------------------------------------------------------
__global__ void transpose_split_kernel(const float* __restrict__ in,
                                       __nv_bfloat16* __restrict__ thi,
                                       __nv_bfloat16* __restrict__ tlo, int R, int C)
{
    __shared__ float t[32][33];
    int c0 = blockIdx.x * 32, r0 = blockIdx.y * 32;
    int tx = threadIdx.x, ty = threadIdx.y;  // 32 x 8
#pragma unroll
    for (int j = 0; j < 4; ++j)
        t[ty + 8 * j][tx] = in[(long long)(r0 + ty + 8 * j) * C + c0 + tx];
    __syncthreads();
#pragma unroll
    for (int j = 0; j < 4; ++j) {
        float v = t[tx][ty + 8 * j];  // in[r0+tx][c0+ty+8j]
        __nv_bfloat16 h = __float2bfloat16(v);
        long long o = (long long)(c0 + ty + 8 * j) * R + r0 + tx;
        thi[o] = h;
        tlo[o] = __float2bfloat16(v - __bfloat162float(h));
    }
}

// ---------------------------------------------------------------------------
// Scratch (single __device__ arena; no allocations anywhere)
// ---------------------------------------------------------------------------
static constexpr size_t SZ_AX = (size_t)8192 * 1024;  // A / X elems
static constexpr size_t SZ_W  = (size_t)512 * 1024;
static constexpr size_t SZ_QK = (size_t)8192 * 512;
static constexpr size_t SZ_S  = (size_t)8192 * 8192;

static constexpr size_t OFF_AHI  = 0;
static constexpr size_t OFF_ALO  = OFF_AHI  + SZ_AX * 2;
static constexpr size_t OFF_XHI  = OFF_ALO  + SZ_AX * 2;
static constexpr size_t OFF_XLO  = OFF_XHI  + SZ_AX * 2;
static constexpr size_t OFF_WQHI = OFF_XLO  + SZ_AX * 2;
static constexpr size_t OFF_WQLO = OFF_WQHI + SZ_W * 2;
static constexpr size_t OFF_WKHI = OFF_WQLO + SZ_W * 2;
static constexpr size_t OFF_WKLO = OFF_WKHI + SZ_W * 2;
static constexpr size_t OFF_Q    = OFF_WKLO + SZ_W * 2;
static constexpr size_t OFF_K    = OFF_Q    + SZ_QK * 4;
static constexpr size_t OFF_QHI  = OFF_K    + SZ_QK * 4;
static constexpr size_t OFF_QLO  = OFF_QHI  + SZ_QK * 2;
static constexpr size_t OFF_KHI  = OFF_QLO  + SZ_QK * 2;
static constexpr size_t OFF_KLO  = OFF_KHI  + SZ_QK * 2;
static constexpr size_t OFF_S    = OFF_KLO  + SZ_QK * 2;
static constexpr size_t OFF_PHI  = OFF_S    + SZ_S * 4;
static constexpr size_t OFF_PLO  = OFF_PHI  + SZ_S * 2;
static constexpr size_t OFF_XTHI = OFF_PLO  + SZ_S * 2;
static constexpr size_t OFF_XTLO = OFF_XTHI + SZ_AX * 2;
static constexpr size_t SCRATCH_TOTAL = OFF_XTLO + SZ_AX * 2;

__device__ __align__(256) unsigned char g_scratch[SCRATCH_TOTAL];

// ---------------------------------------------------------------------------
// kernel_launch
// ---------------------------------------------------------------------------
extern "C" void kernel_launch(void* const* d_in, const int* in_sizes, int n_in,
                              void* d_out, int out_size)
{
    const float* A  = (const float*)d_in[0];
    const float* X  = (const float*)d_in[1];
    const float* Wq = (const float*)d_in[2];
    const float* bq = (const float*)d_in[3];
    const float* Wk = (const float*)d_in[4];
    const float* bk = (const float*)d_in[5];
    float* out = (float*)d_out;

    unsigned char* s = nullptr;
    cudaGetSymbolAddress((void**)&s, g_scratch);
    auto BF = [&](size_t off) { return (__nv_bfloat16*)(s + off); };
    auto F  = [&](size_t off) { return (float*)(s + off); };

    cudaFuncSetAttribute(gemm_split_kernel,
                         cudaFuncAttributeMaxDynamicSharedMemorySize, GEMM_SMEM);

    // Split inputs into bf16 hi/lo
    split_kernel<<<2048, 256>>>(A,  BF(OFF_AHI),  BF(OFF_ALO),  (long long)SZ_AX);
    split_kernel<<<2048, 256>>>(X,  BF(OFF_XHI),  BF(OFF_XLO),  (long long)SZ_AX);
    split_kernel<<<512,  256>>>(Wq, BF(OFF_WQHI), BF(OFF_WQLO), (long long)SZ_W);
    split_kernel<<<512,  256>>>(Wk, BF(OFF_WKHI), BF(OFF_WKLO), (long long)SZ_W);

    // Q = A @ Wq^T + bq ; K = X @ Wk^T + bk   (M=8192, N=512, K=1024)
    dim3 gq(512 / 128, 8192 / 128);
    gemm_split_kernel<<<gq, 256, GEMM_SMEM>>>(
        BF(OFF_AHI), BF(OFF_ALO), BF(OFF_WQHI), BF(OFF_WQLO),
        F(OFF_Q), 8192, 512, 1024, bq);
    gemm_split_kernel<<<gq, 256, GEMM_SMEM>>>(
        BF(OFF_XHI), BF(OFF_XLO), BF(OFF_WKHI), BF(OFF_WKLO),
        F(OFF_K), 8192, 512, 1024, bk);

    split_kernel<<<2048, 256>>>(F(OFF_Q), BF(OFF_QHI), BF(OFF_QLO), (long long)SZ_QK);
    split_kernel<<<2048, 256>>>(F(OFF_K), BF(OFF_KHI), BF(OFF_KLO), (long long)SZ_QK);

    // S = Q @ K^T   (M=8192, N=8192, K=512)
    dim3 gs(8192 / 128, 8192 / 128);
    gemm_split_kernel<<<gs, 256, GEMM_SMEM>>>(
        BF(OFF_QHI), BF(OFF_QLO), BF(OFF_KHI), BF(OFF_KLO),
        F(OFF_S), 8192, 8192, 512, nullptr);

    // P = softmax(S) -> split bf16
    softmax_split_kernel<<<8192, 256>>>(F(OFF_S), BF(OFF_PHI), BF(OFF_PLO), 8192);

    // X^T for the final GEMM's B operand (K-major [1024, 8192])
    transpose_split_kernel<<<dim3(1024 / 32, 8192 / 32), dim3(32, 8)>>>(
        X, BF(OFF_XTHI), BF(OFF_XTLO), 8192, 1024);

    // O = P @ X = P @ (X^T)^T   (M=8192, N=1024, K=8192)
    dim3 go(1024 / 128, 8192 / 128);
    gemm_split_kernel<<<go, 256, GEMM_SMEM>>>(
        BF(OFF_PHI), BF(OFF_PLO), BF(OFF_XTHI), BF(OFF_XTLO),
        out, 8192, 1024, 8192, nullptr);
}

// round 3
// speedup vs baseline: 1.2527x; 1.2527x over previous
#include <cuda_runtime.h>
#include <cuda_bf16.h>
#include <cuda_fp16.h>
#include <cstdint>

// ============================================================================
// AWAttention on B200, baseline sm_100 mma.sync path.
//   Q = A@Wq^T + bq ; K = X@Wk^T + bk ; S = Q@K^T ; P = softmax(S) ; O = P@X
// GEMM modes:
//   ABM=0: split-bf16 3-MMA (hh+hl+lh)  — Q/K/S (precision-critical)
//   ABM=1: fp16 A (single) x fp16 B (hi+lo) 2-MMA — O (P row-stochastic)
// OUT modes: 0 = fp32 C ; 1 = split-bf16 (Chi,Clo) for Q/K feeding S GEMM.
// ============================================================================

#define SWZ(x) ((x) ^ (((x) >> 3) & 0x70))

__device__ __forceinline__ uint32_t smem_u32(const void* p) {
    uint32_t a;
    asm("{ .reg .u64 t; cvta.to.shared.u64 t, %1; cvt.u32.u64 %0, t; }" : "=r"(a) : "l"(p));
    return a;
}

#define CP_ASYNC16(sm, gm) \
    asm volatile("cp.async.cg.shared.global [%0], [%1], 16;" :: "r"(sm), "l"(gm))
#define CP_COMMIT() asm volatile("cp.async.commit_group;" ::: "memory")

__device__ __forceinline__ void ldmx4(uint32_t r[4], uint32_t addr) {
    asm volatile("ldmatrix.sync.aligned.m8n8.x4.shared.b16 {%0,%1,%2,%3}, [%4];"
                 : "=r"(r[0]), "=r"(r[1]), "=r"(r[2]), "=r"(r[3]) : "r"(addr));
}

__device__ __forceinline__ void mma_bf16(float c[4], const uint32_t a[4],
                                         uint32_t b0, uint32_t b1) {
    asm volatile(
        "mma.sync.aligned.m16n8k16.row.col.f32.bf16.bf16.f32 "
        "{%0,%1,%2,%3}, {%4,%5,%6,%7}, {%8,%9}, {%0,%1,%2,%3};"
        : "+f"(c[0]), "+f"(c[1]), "+f"(c[2]), "+f"(c[3])
        : "r"(a[0]), "r"(a[1]), "r"(a[2]), "r"(a[3]), "r"(b0), "r"(b1));
}

__device__ __forceinline__ void mma_f16(float c[4], const uint32_t a[4],
                                        uint32_t b0, uint32_t b1) {
    asm volatile(
        "mma.sync.aligned.m16n8k16.row.col.f32.f16.f16.f32 "
        "{%0,%1,%2,%3}, {%4,%5,%6,%7}, {%8,%9}, {%0,%1,%2,%3};"
        : "+f"(c[0]), "+f"(c[1]), "+f"(c[2]), "+f"(c[3])
        : "r"(a[0]), "r"(a[1]), "r"(a[2]), "r"(a[3]), "r"(b0), "r"(b1));
}

static constexpr int TILE_BYTES = 128 * 128;  // 128 rows x 128B (64 x 16-bit)

// ABM=0: 4 tiles/stage (Ah,Al,Bh,Bl), 3 stages -> 192KB
// ABM=1: 3 tiles/stage (Ah,Bh,Bl),    4 stages -> 192KB
template <int ABM> struct Cfg {
    static constexpr int NT  = (ABM == 0) ? 4 : 3;
    static constexpr int STG = (ABM == 0) ? 3 : 4;
    static constexpr int STAGE_B = NT * TILE_BYTES;
    static constexpr int SMEM = STG * STAGE_B;
};

template <int ABM>
__device__ __forceinline__ void load_chunk(
    uint32_t stage, const uint16_t* __restrict__ Ah, const uint16_t* __restrict__ Al,
    const uint16_t* __restrict__ Bh, const uint16_t* __restrict__ Bl,
    int m0, int n0, int kc, int K, int tid)
{
#pragma unroll
    for (int i = 0; i < 4; ++i) {
        int ch  = tid + i * 256;  // 0..1023
        int row = ch >> 3;
        int c16 = ch & 7;
        uint32_t soff = SWZ((uint32_t)(row * 128 + c16 * 16));
        size_t ga = ((size_t)(m0 + row) * K + (size_t)kc * 64) * 2 + (size_t)c16 * 16;
        size_t gb = ((size_t)(n0 + row) * K + (size_t)kc * 64) * 2 + (size_t)c16 * 16;
        if (ABM == 0) {
            CP_ASYNC16(stage + 0 * TILE_BYTES + soff, (const char*)Ah + ga);
            CP_ASYNC16(stage + 1 * TILE_BYTES + soff, (const char*)Al + ga);
            CP_ASYNC16(stage + 2 * TILE_BYTES + soff, (const char*)Bh + gb);
            CP_ASYNC16(stage + 3 * TILE_BYTES + soff, (const char*)Bl + gb);
        } else {
            CP_ASYNC16(stage + 0 * TILE_BYTES + soff, (const char*)Ah + ga);
            CP_ASYNC16(stage + 1 * TILE_BYTES + soff, (const char*)Bh + gb);
            CP_ASYNC16(stage + 2 * TILE_BYTES + soff, (const char*)Bl + gb);
        }
    }
}

template <int ABM, int OUTM>
__global__ void __launch_bounds__(256, 1) gemm_kernel(
    const uint16_t* __restrict__ Ah, const uint16_t* __restrict__ Al,
    const uint16_t* __restrict__ Bh, const uint16_t* __restrict__ Bl,
    float* __restrict__ C, __nv_bfloat16* __restrict__ Chi,
    __nv_bfloat16* __restrict__ Clo, int M, int N, int K,
    const float* __restrict__ bias)
{
    constexpr int STG = Cfg<ABM>::STG;
    constexpr int STAGE_B = Cfg<ABM>::STAGE_B;

    extern __shared__ __align__(1024) unsigned char smem[];
    uint32_t sbase = smem_u32(smem);
    int tid = threadIdx.x, wid = tid >> 5, lane = tid & 31;
    int warp_m = wid & 1;   // 2 warps over M -> 64 rows
    int warp_n = wid >> 1;  // 4 warps over N -> 32 cols
    int m0 = blockIdx.y * 128, n0 = blockIdx.x * 128;

    float acc[4][4][4];
#pragma unroll
    for (int i = 0; i < 4; ++i)
#pragma unroll
        for (int j = 0; j < 4; ++j)
#pragma unroll
            for (int e = 0; e < 4; ++e) acc[i][j][e] = 0.0f;

    const int nch = K >> 6;

#pragma unroll
    for (int s = 0; s < STG - 1; ++s) {
        if (s < nch)
            load_chunk<ABM>(sbase + s * STAGE_B, Ah, Al, Bh, Bl, m0, n0, s, K, tid);
        CP_COMMIT();
    }

    const int a_rowbase = warp_m * 64 + (lane & 15);
    const int a_colb    = (lane >> 4) * 16;
    const int b_rowbase = warp_n * 32 + (lane & 7) + ((lane >> 3) & 1) * 8;
    const int b_colb    = (lane >> 4) * 16;

    for (int c = 0; c < nch; ++c) {
        if (STG == 3) asm volatile("cp.async.wait_group 1;" ::: "memory");
        else          asm volatile("cp.async.wait_group 2;" ::: "memory");
        __syncthreads();

        int nextc = c + STG - 1;
        if (nextc < nch)
            load_chunk<ABM>(sbase + (uint32_t)(nextc % STG) * STAGE_B,
                            Ah, Al, Bh, Bl, m0, n0, nextc, K, tid);
        CP_COMMIT();

        uint32_t st = sbase + (uint32_t)(c % STG) * STAGE_B;

#pragma unroll
        for (int ks = 0; ks < 4; ++ks) {
            if (ABM == 0) {
                uint32_t tAh = st, tAl = st + TILE_BYTES;
                uint32_t tBh = st + 2 * TILE_BYTES, tBl = st + 3 * TILE_BYTES;
                uint32_t ah[4][4], al[4][4];
#pragma unroll
                for (int i = 0; i < 4; ++i) {
                    uint32_t off = SWZ((uint32_t)((a_rowbase + i * 16) * 128 + ks * 32 + a_colb));
                    ldmx4(ah[i], tAh + off);
                    ldmx4(al[i], tAl + off);
                }
                uint32_t bh[4][2], bl[4][2];
#pragma unroll
                for (int jb = 0; jb < 2; ++jb) {
                    uint32_t off = SWZ((uint32_t)((b_rowbase + jb * 16) * 128 + ks * 32 + b_colb));
                    uint32_t r[4];
                    ldmx4(r, tBh + off);
                    bh[jb * 2 + 0][0] = r[0]; bh[jb * 2 + 0][1] = r[2];
                    bh[jb * 2 + 1][0] = r[1]; bh[jb * 2 + 1][1] = r[3];
                    ldmx4(r, tBl + off);
                    bl[jb * 2 + 0][0] = r[0]; bl[jb * 2 + 0][1] = r[2];
                    bl[jb * 2 + 1][0] = r[1]; bl[jb * 2 + 1][1] = r[3];
                }
#pragma unroll
                for (int i = 0; i < 4; ++i)
#pragma unroll
                    for (int j = 0; j < 4; ++j) {
                        mma_bf16(acc[i][j], ah[i], bh[j][0], bh[j][1]);
                        mma_bf16(acc[i][j], ah[i], bl[j][0], bl[j][1]);
                        mma_bf16(acc[i][j], al[i], bh[j][0], bh[j][1]);
                    }
            } else {
                uint32_t tAh = st;
                uint32_t tBh = st + TILE_BYTES, tBl = st + 2 * TILE_BYTES;
                uint32_t ah[4][4];
#pragma unroll
                for (int i = 0; i < 4; ++i) {
                    uint32_t off = SWZ((uint32_t)((a_rowbase + i * 16) * 128 + ks * 32 + a_colb));
                    ldmx4(ah[i], tAh + off);
                }
                uint32_t bh[4][2], bl[4][2];
#pragma unroll
                for (int jb = 0; jb < 2; ++jb) {
                    uint32_t off = SWZ((uint32_t)((b_rowbase + jb * 16) * 128 + ks * 32 + b_colb));
                    uint32_t r[4];
                    ldmx4(r, tBh + off);
                    bh[jb * 2 + 0][0] = r[0]; bh[jb * 2 + 0][1] = r[2];
                    bh[jb * 2 + 1][0] = r[1]; bh[jb * 2 + 1][1] = r[3];
                    ldmx4(r, tBl + off);
                    bl[jb * 2 + 0][0] = r[0]; bl[jb * 2 + 0][1] = r[2];
                    bl[jb * 2 + 1][0] = r[1]; bl[jb * 2 + 1][1] = r[3];
                }
#pragma unroll
                for (int i = 0; i < 4; ++i)
#pragma unroll
                    for (int j = 0; j < 4; ++j) {
                        mma_f16(acc[i][j], ah[i], bh[j][0], bh[j][1]);
                        mma_f16(acc[i][j], ah[i], bl[j][0], bl[j][1]);
                    }
            }
        }
        __syncthreads();
    }

    // Epilogue
    int g = lane >> 2, t = lane & 3;
#pragma unroll
    for (int i = 0; i < 4; ++i) {
        int r0 = m0 + warp_m * 64 + i * 16 + g;
#pragma unroll
        for (int j = 0; j < 4; ++j) {
            int col = n0 + warp_n * 32 + j * 8 + t * 2;
            float b0 = 0.0f, b1 = 0.0f;
            if (bias) { b0 = __ldg(bias + col); b1 = __ldg(bias + col + 1); }
            float v0 = acc[i][j][0] + b0, v1 = acc[i][j][1] + b1;
            float v2 = acc[i][j][2] + b0, v3 = acc[i][j][3] + b1;
            if (OUTM == 0) {
                *(float2*)(C + (size_t)r0 * N + col)       = make_float2(v0, v1);
                *(float2*)(C + (size_t)(r0 + 8) * N + col) = make_float2(v2, v3);
            } else {
                __nv_bfloat16 h0 = __float2bfloat16(v0), h1 = __float2bfloat16(v1);
                __nv_bfloat16 h2 = __float2bfloat16(v2), h3 = __float2bfloat16(v3);
                __nv_bfloat16 l0 = __float2bfloat16(v0 - __bfloat162float(h0));
                __nv_bfloat16 l1 = __float2bfloat16(v1 - __bfloat162float(h1));
                __nv_bfloat16 l2 = __float2bfloat16(v2 - __bfloat162float(h2));
                __nv_bfloat16 l3 = __float2bfloat16(v3 - __bfloat162float(h3));
                __nv_bfloat162 hh0; hh0.x = h0; hh0.y = h1;
                __nv_bfloat162 hh1; hh1.x = h2; hh1.y = h3;
                __nv_bfloat162 ll0; ll0.x = l0; ll0.y = l1;
                __nv_bfloat162 ll1; ll1.x = l2; ll1.y = l3;
                *(__nv_bfloat162*)(Chi + (size_t)r0 * N + col)       = hh0;
                *(__nv_bfloat162*)(Chi + (size_t)(r0 + 8) * N + col) = hh1;
                *(__nv_bfloat162*)(Clo + (size_t)r0 * N + col)       = ll0;
                *(__nv_bfloat162*)(Clo + (size_t)(r0 + 8) * N + col) = ll1;
            }
        }
    }
}

// ---------------------------------------------------------------------------
// fp32 -> (bf16 hi, bf16 lo) split
// ---------------------------------------------------------------------------
__global__ void split_kernel(const float* __restrict__ in,
                             __nv_bfloat16* __restrict__ hi,
                             __nv_bfloat16* __restrict__ lo, long long n)
{
    long long i = (long long)blockIdx.x * blockDim.x + threadIdx.x;
    long long stride = (long long)gridDim.x * blockDim.x;
    for (; i < n; i += stride) {
        float x = in[i];
        __nv_bfloat16 h = __float2bfloat16(x);
        hi[i] = h;
        lo[i] = __float2bfloat16(x - __bfloat162float(h));
    }
}

// ---------------------------------------------------------------------------
// Row softmax (N<=8192) writing fp16 probabilities
// ---------------------------------------------------------------------------
__global__ void __launch_bounds__(256) softmax_kernel(
    const float* __restrict__ S, __half* __restrict__ P, int N)
{
    __shared__ float buf[8192];
    __shared__ float red[8];
    int row = blockIdx.x, tid = threadIdx.x;
    const float* s = S + (long long)row * N;

    float mx = -3.0e38f;
    for (int i = tid; i < N; i += 256) mx = fmaxf(mx, s[i]);
#pragma unroll
    for (int o = 16; o; o >>= 1) mx = fmaxf(mx, __shfl_xor_sync(0xFFFFFFFFu, mx, o));
    if ((tid & 31) == 0) red[tid >> 5] = mx;
    __syncthreads();
    mx = red[0];
#pragma unroll
    for (int w = 1; w < 8; ++w) mx = fmaxf(mx, red[w]);

    float sum = 0.0f;
    for (int i = tid; i < N; i += 256) {
        float e = __expf(s[i] - mx);
        buf[i] = e;
        sum += e;
    }
#pragma unroll
    for (int o = 16; o; o >>= 1) sum += __shfl_xor_sync(0xFFFFFFFFu, sum, o);
    __syncthreads();
    if ((tid & 31) == 0) red[tid >> 5] = sum;
    __syncthreads();
    sum = 0.0f;
#pragma unroll
    for (int w = 0; w < 8; ++w) sum += red[w];
    float inv = 1.0f / sum;

    for (int i = tid; i < N; i += 256)
        P[(long long)row * N + i] = __float2half(buf[i] * inv);
}

// ---------------------------------------------------------------------------
// Transpose fp32 [R,C] -> split-fp16 [C,R]
// ---------------------------------------------------------------------------
__global__ void transpose_split_kernel(const float* __restrict__ in,
                                       __half* __restrict__ thi,
                                       __half* __restrict__ tlo, int R, int C)
{
    __shared__ float t[32][33];
    int c0 = blockIdx.x * 32, r0 = blockIdx.y * 32;
    int tx = threadIdx.x, ty = threadIdx.y;  // 32 x 8
#pragma unroll
    for (int j = 0; j < 4; ++j)
        t[ty + 8 * j][tx] = in[(long long)(r0 + ty + 8 * j) * C + c0 + tx];
    __syncthreads();
#pragma unroll
    for (int j = 0; j < 4; ++j) {
        float v = t[tx][ty + 8 * j];  // in[r0+tx][c0+ty+8j]
        __half h = __float2half(v);
        long long o = (long long)(c0 + ty + 8 * j) * R + r0 + tx;
        thi[o] = h;
        tlo[o] = __float2half(v - __half2float(h));
    }
}

// ---------------------------------------------------------------------------
// Scratch
// ---------------------------------------------------------------------------
static constexpr size_t SZ_AX = (size_t)8192 * 1024;
static constexpr size_t SZ_W  = (size_t)512 * 1024;
static constexpr size_t SZ_QK = (size_t)8192 * 512;
static constexpr size_t SZ_S  = (size_t)8192 * 8192;

static constexpr size_t OFF_AHI  = 0;
static constexpr size_t OFF_ALO  = OFF_AHI  + SZ_AX * 2;
static constexpr size_t OFF_XHI  = OFF_ALO  + SZ_AX * 2;
static constexpr size_t OFF_XLO  = OFF_XHI  + SZ_AX * 2;
static constexpr size_t OFF_WQHI = OFF_XLO  + SZ_AX * 2;
static constexpr size_t OFF_WQLO = OFF_WQHI + SZ_W * 2;
static constexpr size_t OFF_WKHI = OFF_WQLO + SZ_W * 2;
static constexpr size_t OFF_WKLO = OFF_WKHI + SZ_W * 2;
static constexpr size_t OFF_QHI  = OFF_WKLO + SZ_W * 2;
static constexpr size_t OFF_QLO  = OFF_QHI  + SZ_QK * 2;
static constexpr size_t OFF_KHI  = OFF_QLO  + SZ_QK * 2;
static constexpr size_t OFF_KLO  = OFF_KHI  + SZ_QK * 2;
static constexpr size_t OFF_S    = OFF_KLO  + SZ_QK * 2;
static constexpr size_t OFF_PHI  = OFF_S    + SZ_S * 4;
static constexpr size_t OFF_XTHI = OFF_PHI  + SZ_S * 2;
static constexpr size_t OFF_XTLO = OFF_XTHI + SZ_AX * 2;
static constexpr size_t SCRATCH_TOTAL = OFF_XTLO + SZ_AX * 2;

__device__ __align__(256) unsigned char g_scratch[SCRATCH_TOTAL];

// ---------------------------------------------------------------------------
// kernel_launch
// ---------------------------------------------------------------------------
extern "C" void kernel_launch(void* const* d_in, const int* in_sizes, int n_in,
                              void* d_out, int out_size)
{
    const float* A  = (const float*)d_in[0];
    const float* X  = (const float*)d_in[1];
    const float* Wq = (const float*)d_in[2];
    const float* bq = (const float*)d_in[3];
    const float* Wk = (const float*)d_in[4];
    const float* bk = (const float*)d_in[5];
    float* out = (float*)d_out;

    unsigned char* s = nullptr;
    cudaGetSymbolAddress((void**)&s, g_scratch);
    auto BF = [&](size_t off) { return (__nv_bfloat16*)(s + off); };
    auto U16 = [&](size_t off) { return (const uint16_t*)(s + off); };
    auto F  = [&](size_t off) { return (float*)(s + off); };

    cudaFuncSetAttribute(gemm_kernel<0, 0>,
                         cudaFuncAttributeMaxDynamicSharedMemorySize, Cfg<0>::SMEM);
    cudaFuncSetAttribute(gemm_kernel<0, 1>,
                         cudaFuncAttributeMaxDynamicSharedMemorySize, Cfg<0>::SMEM);
    cudaFuncSetAttribute(gemm_kernel<1, 0>,
                         cudaFuncAttributeMaxDynamicSharedMemorySize, Cfg<1>::SMEM);

    // Split inputs into bf16 hi/lo
    split_kernel<<<2048, 256>>>(A,  BF(OFF_AHI),  BF(OFF_ALO),  (long long)SZ_AX);
    split_kernel<<<2048, 256>>>(X,  BF(OFF_XHI),  BF(OFF_XLO),  (long long)SZ_AX);
    split_kernel<<<512,  256>>>(Wq, BF(OFF_WQHI), BF(OFF_WQLO), (long long)SZ_W);
    split_kernel<<<512,  256>>>(Wk, BF(OFF_WKHI), BF(OFF_WKLO), (long long)SZ_W);

    // Q/K GEMMs with fused split-bf16 epilogue (M=8192, N=512, K=1024)
    dim3 gq(512 / 128, 8192 / 128);
    gemm_kernel<0, 1><<<gq, 256, Cfg<0>::SMEM>>>(
        U16(OFF_AHI), U16(OFF_ALO), U16(OFF_WQHI), U16(OFF_WQLO),
        nullptr, BF(OFF_QHI), BF(OFF_QLO), 8192, 512, 1024, bq);
    gemm_kernel<0, 1><<<gq, 256, Cfg<0>::SMEM>>>(
        U16(OFF_XHI), U16(OFF_XLO), U16(OFF_WKHI), U16(OFF_WKLO),
        nullptr, BF(OFF_KHI), BF(OFF_KLO), 8192, 512, 1024, bk);

    // S = Q @ K^T   (M=8192, N=8192, K=512)
    dim3 gs(8192 / 128, 8192 / 128);
    gemm_kernel<0, 0><<<gs, 256, Cfg<0>::SMEM>>>(
        U16(OFF_QHI), U16(OFF_QLO), U16(OFF_KHI), U16(OFF_KLO),
        F(OFF_S), nullptr, nullptr, 8192, 8192, 512, nullptr);

    // P = softmax(S) -> fp16
    softmax_kernel<<<8192, 256>>>(F(OFF_S), (__half*)(s + OFF_PHI), 8192);

    // X^T -> split fp16, K-major [1024, 8192]
    transpose_split_kernel<<<dim3(1024 / 32, 8192 / 32), dim3(32, 8)>>>(
        X, (__half*)(s + OFF_XTHI), (__half*)(s + OFF_XTLO), 8192, 1024);

    // O = P @ X   (M=8192, N=1024, K=8192), fp16 2-MMA
    dim3 go(1024 / 128, 8192 / 128);
    gemm_kernel<1, 0><<<go, 256, Cfg<1>::SMEM>>>(
        U16(OFF_PHI), nullptr, U16(OFF_XTHI), U16(OFF_XTLO),
        out, nullptr, nullptr, 8192, 1024, 8192, nullptr);
}

// round 4
// speedup vs baseline: 1.5659x; 1.2500x over previous
#include <cuda_runtime.h>
#include <cuda_bf16.h>
#include <cuda_fp16.h>
#include <cstdint>

// ============================================================================
// AWAttention on B200, baseline sm_100 mma.sync path.
//   Q = A@Wq^T + bq ; K = X@Wk^T + bk ; S = Q@K^T ; P = softmax(S) ; O = P@X
// GEMM modes:
//   ABM=0: split-bf16 3-MMA (hh+hl+lh)  — Q/K/S (precision-critical)
//   ABM=2: plain fp16 1-MMA             — O (P row-stochastic, near-one-hot)
// OUT modes: 0 = fp32 C ; 1 = split-bf16 (Chi,Clo) for Q/K feeding S GEMM.
// ============================================================================

#define SWZ(x) ((x) ^ (((x) >> 3) & 0x70))

__device__ __forceinline__ uint32_t smem_u32(const void* p) {
    uint32_t a;
    asm("{ .reg .u64 t; cvta.to.shared.u64 t, %1; cvt.u32.u64 %0, t; }" : "=r"(a) : "l"(p));
    return a;
}

#define CP_ASYNC16(sm, gm) \
    asm volatile("cp.async.cg.shared.global [%0], [%1], 16;" :: "r"(sm), "l"(gm))
#define CP_COMMIT() asm volatile("cp.async.commit_group;" ::: "memory")

__device__ __forceinline__ void ldmx4(uint32_t r[4], uint32_t addr) {
    asm volatile("ldmatrix.sync.aligned.m8n8.x4.shared.b16 {%0,%1,%2,%3}, [%4];"
                 : "=r"(r[0]), "=r"(r[1]), "=r"(r[2]), "=r"(r[3]) : "r"(addr));
}

__device__ __forceinline__ void mma_bf16(float c[4], const uint32_t a[4],
                                         uint32_t b0, uint32_t b1) {
    asm volatile(
        "mma.sync.aligned.m16n8k16.row.col.f32.bf16.bf16.f32 "
        "{%0,%1,%2,%3}, {%4,%5,%6,%7}, {%8,%9}, {%0,%1,%2,%3};"
        : "+f"(c[0]), "+f"(c[1]), "+f"(c[2]), "+f"(c[3])
        : "r"(a[0]), "r"(a[1]), "r"(a[2]), "r"(a[3]), "r"(b0), "r"(b1));
}

__device__ __forceinline__ void mma_f16(float c[4], const uint32_t a[4],
                                        uint32_t b0, uint32_t b1) {
    asm volatile(
        "mma.sync.aligned.m16n8k16.row.col.f32.f16.f16.f32 "
        "{%0,%1,%2,%3}, {%4,%5,%6,%7}, {%8,%9}, {%0,%1,%2,%3};"
        : "+f"(c[0]), "+f"(c[1]), "+f"(c[2]), "+f"(c[3])
        : "r"(a[0]), "r"(a[1]), "r"(a[2]), "r"(a[3]), "r"(b0), "r"(b1));
}

static constexpr int TILE_BYTES = 128 * 128;  // 128 rows x 128B (64 x 16-bit)

// ABM=0: 4 tiles/stage (Ah,Al,Bh,Bl), 3 stages -> 192KB
// ABM=2: 2 tiles/stage (Ah,Bh),       6 stages -> 192KB
template <int ABM> struct Cfg {
    static constexpr int NT  = (ABM == 0) ? 4 : 2;
    static constexpr int STG = (ABM == 0) ? 3 : 6;
    static constexpr int STAGE_B = NT * TILE_BYTES;
    static constexpr int SMEM = STG * STAGE_B;
};

template <int ABM>
__device__ __forceinline__ void load_chunk(
    uint32_t stage, const uint16_t* __restrict__ Ah, const uint16_t* __restrict__ Al,
    const uint16_t* __restrict__ Bh, const uint16_t* __restrict__ Bl,
    int m0, int n0, int kc, int K, int tid)
{
#pragma unroll
    for (int i = 0; i < 4; ++i) {
        int ch  = tid + i * 256;  // 0..1023
        int row = ch >> 3;
        int c16 = ch & 7;
        uint32_t soff = SWZ((uint32_t)(row * 128 + c16 * 16));
        size_t ga = ((size_t)(m0 + row) * K + (size_t)kc * 64) * 2 + (size_t)c16 * 16;
        size_t gb = ((size_t)(n0 + row) * K + (size_t)kc * 64) * 2 + (size_t)c16 * 16;
        if (ABM == 0) {
            CP_ASYNC16(stage + 0 * TILE_BYTES + soff, (const char*)Ah + ga);
            CP_ASYNC16(stage + 1 * TILE_BYTES + soff, (const char*)Al + ga);
            CP_ASYNC16(stage + 2 * TILE_BYTES + soff, (const char*)Bh + gb);
            CP_ASYNC16(stage + 3 * TILE_BYTES + soff, (const char*)Bl + gb);
        } else {
            CP_ASYNC16(stage + 0 * TILE_BYTES + soff, (const char*)Ah + ga);
            CP_ASYNC16(stage + 1 * TILE_BYTES + soff, (const char*)Bh + gb);
        }
    }
}

template <int ABM, int OUTM>
__global__ void __launch_bounds__(256, 1) gemm_kernel(
    const uint16_t* __restrict__ Ah, const uint16_t* __restrict__ Al,
    const uint16_t* __restrict__ Bh, const uint16_t* __restrict__ Bl,
    float* __restrict__ C, __nv_bfloat16* __restrict__ Chi,
    __nv_bfloat16* __restrict__ Clo, int M, int N, int K,
    const float* __restrict__ bias)
{
    constexpr int STG = Cfg<ABM>::STG;
    constexpr int STAGE_B = Cfg<ABM>::STAGE_B;

    extern __shared__ __align__(1024) unsigned char smem[];
    uint32_t sbase = smem_u32(smem);
    int tid = threadIdx.x, wid = tid >> 5, lane = tid & 31;
    int warp_m = wid & 1;   // 2 warps over M -> 64 rows
    int warp_n = wid >> 1;  // 4 warps over N -> 32 cols
    int m0 = blockIdx.y * 128, n0 = blockIdx.x * 128;

    float acc[4][4][4];
#pragma unroll
    for (int i = 0; i < 4; ++i)
#pragma unroll
        for (int j = 0; j < 4; ++j)
#pragma unroll
            for (int e = 0; e < 4; ++e) acc[i][j][e] = 0.0f;

    const int nch = K >> 6;

#pragma unroll
    for (int s = 0; s < STG - 1; ++s) {
        if (s < nch)
            load_chunk<ABM>(sbase + s * STAGE_B, Ah, Al, Bh, Bl, m0, n0, s, K, tid);
        CP_COMMIT();
    }

    const int a_rowbase = warp_m * 64 + (lane & 15);
    const int a_colb    = (lane >> 4) * 16;
    const int b_rowbase = warp_n * 32 + (lane & 7) + ((lane >> 3) & 1) * 8;
    const int b_colb    = (lane >> 4) * 16;

    for (int c = 0; c < nch; ++c) {
        if constexpr (STG == 3)      asm volatile("cp.async.wait_group 1;" ::: "memory");
        else if constexpr (STG == 6) asm volatile("cp.async.wait_group 4;" ::: "memory");
        else                         asm volatile("cp.async.wait_group 2;" ::: "memory");
        __syncthreads();

        int nextc = c + STG - 1;
        if (nextc < nch)
            load_chunk<ABM>(sbase + (uint32_t)(nextc % STG) * STAGE_B,
                            Ah, Al, Bh, Bl, m0, n0, nextc, K, tid);
        CP_COMMIT();

        uint32_t st = sbase + (uint32_t)(c % STG) * STAGE_B;

#pragma unroll
        for (int ks = 0; ks < 4; ++ks) {
            if (ABM == 0) {
                uint32_t tAh = st, tAl = st + TILE_BYTES;
                uint32_t tBh = st + 2 * TILE_BYTES, tBl = st + 3 * TILE_BYTES;
                uint32_t ah[4][4], al[4][4];
#pragma unroll
                for (int i = 0; i < 4; ++i) {
                    uint32_t off = SWZ((uint32_t)((a_rowbase + i * 16) * 128 + ks * 32 + a_colb));
                    ldmx4(ah[i], tAh + off);
                    ldmx4(al[i], tAl + off);
                }
                uint32_t bh[4][2], bl[4][2];
#pragma unroll
                for (int jb = 0; jb < 2; ++jb) {
                    uint32_t off = SWZ((uint32_t)((b_rowbase + jb * 16) * 128 + ks * 32 + b_colb));
                    uint32_t r[4];
                    ldmx4(r, tBh + off);
                    bh[jb * 2 + 0][0] = r[0]; bh[jb * 2 + 0][1] = r[2];
                    bh[jb * 2 + 1][0] = r[1]; bh[jb * 2 + 1][1] = r[3];
                    ldmx4(r, tBl + off);
                    bl[jb * 2 + 0][0] = r[0]; bl[jb * 2 + 0][1] = r[2];
                    bl[jb * 2 + 1][0] = r[1]; bl[jb * 2 + 1][1] = r[3];
                }
#pragma unroll
                for (int i = 0; i < 4; ++i)
#pragma unroll
                    for (int j = 0; j < 4; ++j) {
                        mma_bf16(acc[i][j], ah[i], bh[j][0], bh[j][1]);
                        mma_bf16(acc[i][j], ah[i], bl[j][0], bl[j][1]);
                        mma_bf16(acc[i][j], al[i], bh[j][0], bh[j][1]);
                    }
            } else {
                uint32_t tAh = st;
                uint32_t tBh = st + TILE_BYTES;
                uint32_t ah[4][4];
#pragma unroll
                for (int i = 0; i < 4; ++i) {
                    uint32_t off = SWZ((uint32_t)((a_rowbase + i * 16) * 128 + ks * 32 + a_colb));
                    ldmx4(ah[i], tAh + off);
                }
                uint32_t bh[4][2];
#pragma unroll
                for (int jb = 0; jb < 2; ++jb) {
                    uint32_t off = SWZ((uint32_t)((b_rowbase + jb * 16) * 128 + ks * 32 + b_colb));
                    uint32_t r[4];
                    ldmx4(r, tBh + off);
                    bh[jb * 2 + 0][0] = r[0]; bh[jb * 2 + 0][1] = r[2];
                    bh[jb * 2 + 1][0] = r[1]; bh[jb * 2 + 1][1] = r[3];
                }
#pragma unroll
                for (int i = 0; i < 4; ++i)
#pragma unroll
                    for (int j = 0; j < 4; ++j)
                        mma_f16(acc[i][j], ah[i], bh[j][0], bh[j][1]);
            }
        }
        __syncthreads();
    }

    // Epilogue
    int g = lane >> 2, t = lane & 3;
#pragma unroll
    for (int i = 0; i < 4; ++i) {
        int r0 = m0 + warp_m * 64 + i * 16 + g;
#pragma unroll
        for (int j = 0; j < 4; ++j) {
            int col = n0 + warp_n * 32 + j * 8 + t * 2;
            float b0 = 0.0f, b1 = 0.0f;
            if (bias) { b0 = __ldg(bias + col); b1 = __ldg(bias + col + 1); }
            float v0 = acc[i][j][0] + b0, v1 = acc[i][j][1] + b1;
            float v2 = acc[i][j][2] + b0, v3 = acc[i][j][3] + b1;
            if (OUTM == 0) {
                *(float2*)(C + (size_t)r0 * N + col)       = make_float2(v0, v1);
                *(float2*)(C + (size_t)(r0 + 8) * N + col) = make_float2(v2, v3);
            } else {
                __nv_bfloat16 h0 = __float2bfloat16(v0), h1 = __float2bfloat16(v1);
                __nv_bfloat16 h2 = __float2bfloat16(v2), h3 = __float2bfloat16(v3);
                __nv_bfloat16 l0 = __float2bfloat16(v0 - __bfloat162float(h0));
                __nv_bfloat16 l1 = __float2bfloat16(v1 - __bfloat162float(h1));
                __nv_bfloat16 l2 = __float2bfloat16(v2 - __bfloat162float(h2));
                __nv_bfloat16 l3 = __float2bfloat16(v3 - __bfloat162float(h3));
                __nv_bfloat162 hh0; hh0.x = h0; hh0.y = h1;
                __nv_bfloat162 hh1; hh1.x = h2; hh1.y = h3;
                __nv_bfloat162 ll0; ll0.x = l0; ll0.y = l1;
                __nv_bfloat162 ll1; ll1.x = l2; ll1.y = l3;
                *(__nv_bfloat162*)(Chi + (size_t)r0 * N + col)       = hh0;
                *(__nv_bfloat162*)(Chi + (size_t)(r0 + 8) * N + col) = hh1;
                *(__nv_bfloat162*)(Clo + (size_t)r0 * N + col)       = ll0;
                *(__nv_bfloat162*)(Clo + (size_t)(r0 + 8) * N + col) = ll1;
            }
        }
    }
}

// ---------------------------------------------------------------------------
// fp32 -> (bf16 hi, bf16 lo) split
// ---------------------------------------------------------------------------
__global__ void split_kernel(const float* __restrict__ in,
                             __nv_bfloat16* __restrict__ hi,
                             __nv_bfloat16* __restrict__ lo, long long n)
{
    long long i = (long long)blockIdx.x * blockDim.x + threadIdx.x;
    long long stride = (long long)gridDim.x * blockDim.x;
    for (; i < n; i += stride) {
        float x = in[i];
        __nv_bfloat16 h = __float2bfloat16(x);
        hi[i] = h;
        lo[i] = __float2bfloat16(x - __bfloat162float(h));
    }
}

// ---------------------------------------------------------------------------
// Row softmax (N<=8192) writing fp16 probabilities
// ---------------------------------------------------------------------------
__global__ void __launch_bounds__(256) softmax_kernel(
    const float* __restrict__ S, __half* __restrict__ P, int N)
{
    __shared__ float buf[8192];
    __shared__ float red[8];
    int row = blockIdx.x, tid = threadIdx.x;
    const float* s = S + (long long)row * N;

    float mx = -3.0e38f;
    for (int i = tid; i < N; i += 256) mx = fmaxf(mx, s[i]);
#pragma unroll
    for (int o = 16; o; o >>= 1) mx = fmaxf(mx, __shfl_xor_sync(0xFFFFFFFFu, mx, o));
    if ((tid & 31) == 0) red[tid >> 5] = mx;
    __syncthreads();
    mx = red[0];
#pragma unroll
    for (int w = 1; w < 8; ++w) mx = fmaxf(mx, red[w]);

    float sum = 0.0f;
    for (int i = tid; i < N; i += 256) {
        float e = __expf(s[i] - mx);
        buf[i] = e;
        sum += e;
    }
#pragma unroll
    for (int o = 16; o; o >>= 1) sum += __shfl_xor_sync(0xFFFFFFFFu, sum, o);
    __syncthreads();
    if ((tid & 31) == 0) red[tid >> 5] = sum;
    __syncthreads();
    sum = 0.0f;
#pragma unroll
    for (int w = 0; w < 8; ++w) sum += red[w];
    float inv = 1.0f / sum;

    for (int i = tid; i < N; i += 256)
        P[(long long)row * N + i] = __float2half(buf[i] * inv);
}

// ---------------------------------------------------------------------------
// Transpose fp32 [R,C] -> fp16 [C,R]
// ---------------------------------------------------------------------------
__global__ void transpose_f16_kernel(const float* __restrict__ in,
                                     __half* __restrict__ thi, int R, int C)
{
    __shared__ float t[32][33];
    int c0 = blockIdx.x * 32, r0 = blockIdx.y * 32;
    int tx = threadIdx.x, ty = threadIdx.y;  // 32 x 8
#pragma unroll
    for (int j = 0; j < 4; ++j)
        t[ty + 8 * j][tx] = in[(long long)(r0 + ty + 8 * j) * C + c0 + tx];
    __syncthreads();
#pragma unroll
    for (int j = 0; j < 4; ++j) {
        float v = t[tx][ty + 8 * j];  // in[r0+tx][c0+ty+8j]
        long long o = (long long)(c0 + ty + 8 * j) * R + r0 + tx;
        thi[o] = __float2half(v);
    }
}

// ---------------------------------------------------------------------------
// Scratch
// ---------------------------------------------------------------------------
static constexpr size_t SZ_AX = (size_t)8192 * 1024;
static constexpr size_t SZ_W  = (size_t)512 * 1024;
static constexpr size_t SZ_QK = (size_t)8192 * 512;
static constexpr size_t SZ_S  = (size_t)8192 * 8192;

static constexpr size_t OFF_AHI  = 0;
static constexpr size_t OFF_ALO  = OFF_AHI  + SZ_AX * 2;
static constexpr size_t OFF_XHI  = OFF_ALO  + SZ_AX * 2;
static constexpr size_t OFF_XLO  = OFF_XHI  + SZ_AX * 2;
static constexpr size_t OFF_WQHI = OFF_XLO  + SZ_AX * 2;
static constexpr size_t OFF_WQLO = OFF_WQHI + SZ_W * 2;
static constexpr size_t OFF_WKHI = OFF_WQLO + SZ_W * 2;
static constexpr size_t OFF_WKLO = OFF_WKHI + SZ_W * 2;
static constexpr size_t OFF_QHI  = OFF_WKLO + SZ_W * 2;
static constexpr size_t OFF_QLO  = OFF_QHI  + SZ_QK * 2;
static constexpr size_t OFF_KHI  = OFF_QLO  + SZ_QK * 2;
static constexpr size_t OFF_KLO  = OFF_KHI  + SZ_QK * 2;
static constexpr size_t OFF_S    = OFF_KLO  + SZ_QK * 2;
static constexpr size_t OFF_PHI  = OFF_S    + SZ_S * 4;
static constexpr size_t OFF_XTHI = OFF_PHI  + SZ_S * 2;
static constexpr size_t SCRATCH_TOTAL = OFF_XTHI + SZ_AX * 2;

__device__ __align__(256) unsigned char g_scratch[SCRATCH_TOTAL];

// ---------------------------------------------------------------------------
// kernel_launch
// ---------------------------------------------------------------------------
extern "C" void kernel_launch(void* const* d_in, const int* in_sizes, int n_in,
                              void* d_out, int out_size)
{
    const float* A  = (const float*)d_in[0];
    const float* X  = (const float*)d_in[1];
    const float* Wq = (const float*)d_in[2];
    const float* bq = (const float*)d_in[3];
    const float* Wk = (const float*)d_in[4];
    const float* bk = (const float*)d_in[5];
    float* out = (float*)d_out;

    unsigned char* s = nullptr;
    cudaGetSymbolAddress((void**)&s, g_scratch);
    auto BF = [&](size_t off) { return (__nv_bfloat16*)(s + off); };
    auto U16 = [&](size_t off) { return (const uint16_t*)(s + off); };
    auto F  = [&](size_t off) { return (float*)(s + off); };

    cudaFuncSetAttribute(gemm_kernel<0, 0>,
                         cudaFuncAttributeMaxDynamicSharedMemorySize, Cfg<0>::SMEM);
    cudaFuncSetAttribute(gemm_kernel<0, 1>,
                         cudaFuncAttributeMaxDynamicSharedMemorySize, Cfg<0>::SMEM);
    cudaFuncSetAttribute(gemm_kernel<2, 0>,
                         cudaFuncAttributeMaxDynamicSharedMemorySize, Cfg<2>::SMEM);

    // Split inputs into bf16 hi/lo
    split_kernel<<<2048, 256>>>(A,  BF(OFF_AHI),  BF(OFF_ALO),  (long long)SZ_AX);
    split_kernel<<<2048, 256>>>(X,  BF(OFF_XHI),  BF(OFF_XLO),  (long long)SZ_AX);
    split_kernel<<<512,  256>>>(Wq, BF(OFF_WQHI), BF(OFF_WQLO), (long long)SZ_W);
    split_kernel<<<512,  256>>>(Wk, BF(OFF_WKHI), BF(OFF_WKLO), (long long)SZ_W);

    // Q/K GEMMs with fused split-bf16 epilogue (M=8192, N=512, K=1024)
    dim3 gq(512 / 128, 8192 / 128);
    gemm_kernel<0, 1><<<gq, 256, Cfg<0>::SMEM>>>(
        U16(OFF_AHI), U16(OFF_ALO), U16(OFF_WQHI), U16(OFF_WQLO),
        nullptr, BF(OFF_QHI), BF(OFF_QLO), 8192, 512, 1024, bq);
    gemm_kernel<0, 1><<<gq, 256, Cfg<0>::SMEM>>>(
        U16(OFF_XHI), U16(OFF_XLO), U16(OFF_WKHI), U16(OFF_WKLO),
        nullptr, BF(OFF_KHI), BF(OFF_KLO), 8192, 512, 1024, bk);

    // S = Q @ K^T   (M=8192, N=8192, K=512)
    dim3 gs(8192 / 128, 8192 / 128);
    gemm_kernel<0, 0><<<gs, 256, Cfg<0>::SMEM>>>(
        U16(OFF_QHI), U16(OFF_QLO), U16(OFF_KHI), U16(OFF_KLO),
        F(OFF_S), nullptr, nullptr, 8192, 8192, 512, nullptr);

    // P = softmax(S) -> fp16
    softmax_kernel<<<8192, 256>>>(F(OFF_S), (__half*)(s + OFF_PHI), 8192);

    // X^T -> fp16, K-major [1024, 8192]
    transpose_f16_kernel<<<dim3(1024 / 32, 8192 / 32), dim3(32, 8)>>>(
        X, (__half*)(s + OFF_XTHI), 8192, 1024);

    // O = P @ X   (M=8192, N=1024, K=8192), single fp16 MMA
    dim3 go(1024 / 128, 8192 / 128);
    gemm_kernel<2, 0><<<go, 256, Cfg<2>::SMEM>>>(
        U16(OFF_PHI), nullptr, U16(OFF_XTHI), nullptr,
        out, nullptr, nullptr, 8192, 1024, 8192, nullptr);
}

// round 5
// speedup vs baseline: 1.5705x; 1.0029x over previous
#include <cuda_runtime.h>
#include <cuda_bf16.h>
#include <cuda_fp16.h>
#include <cstdint>

// ============================================================================
// AWAttention on B200, baseline sm_100 mma.sync path.
//   Q = A@Wq^T + bq ; K = X@Wk^T + bk ; S = Q@K^T ; P = softmax(S) ; O = P@X
// GEMM modes:
//   ABM=0: split-bf16 3-MMA (hh+hl+lh)  — Q/K/S (precision-critical)
//          MMAs issued in 3 independent passes to avoid RAW chains.
//   ABM=2: plain fp16 1-MMA             — O (P row-stochastic, near-one-hot)
// OUT modes: 0 = fp32 C ; 1 = split-bf16 (Chi,Clo) for Q/K feeding S GEMM.
// ============================================================================

#define SWZ(x) ((x) ^ (((x) >> 3) & 0x70))

__device__ __forceinline__ uint32_t smem_u32(const void* p) {
    uint32_t a;
    asm("{ .reg .u64 t; cvta.to.shared.u64 t, %1; cvt.u32.u64 %0, t; }" : "=r"(a) : "l"(p));
    return a;
}

#define CP_ASYNC16(sm, gm) \
    asm volatile("cp.async.cg.shared.global [%0], [%1], 16;" :: "r"(sm), "l"(gm))
#define CP_COMMIT() asm volatile("cp.async.commit_group;" ::: "memory")

__device__ __forceinline__ void ldmx4(uint32_t r[4], uint32_t addr) {
    asm volatile("ldmatrix.sync.aligned.m8n8.x4.shared.b16 {%0,%1,%2,%3}, [%4];"
                 : "=r"(r[0]), "=r"(r[1]), "=r"(r[2]), "=r"(r[3]) : "r"(addr));
}

__device__ __forceinline__ void mma_bf16(float c[4], const uint32_t a[4],
                                         uint32_t b0, uint32_t b1) {
    asm volatile(
        "mma.sync.aligned.m16n8k16.row.col.f32.bf16.bf16.f32 "
        "{%0,%1,%2,%3}, {%4,%5,%6,%7}, {%8,%9}, {%0,%1,%2,%3};"
        : "+f"(c[0]), "+f"(c[1]), "+f"(c[2]), "+f"(c[3])
        : "r"(a[0]), "r"(a[1]), "r"(a[2]), "r"(a[3]), "r"(b0), "r"(b1));
}

__device__ __forceinline__ void mma_f16(float c[4], const uint32_t a[4],
                                        uint32_t b0, uint32_t b1) {
    asm volatile(
        "mma.sync.aligned.m16n8k16.row.col.f32.f16.f16.f32 "
        "{%0,%1,%2,%3}, {%4,%5,%6,%7}, {%8,%9}, {%0,%1,%2,%3};"
        : "+f"(c[0]), "+f"(c[1]), "+f"(c[2]), "+f"(c[3])
        : "r"(a[0]), "r"(a[1]), "r"(a[2]), "r"(a[3]), "r"(b0), "r"(b1));
}

static constexpr int TILE_BYTES = 128 * 128;  // 128 rows x 128B (64 x 16-bit)

// ABM=0: 4 tiles/stage (Ah,Al,Bh,Bl), 3 stages -> 192KB
// ABM=2: 2 tiles/stage (Ah,Bh),       6 stages -> 192KB
template <int ABM> struct Cfg {
    static constexpr int NT  = (ABM == 0) ? 4 : 2;
    static constexpr int STG = (ABM == 0) ? 3 : 6;
    static constexpr int STAGE_B = NT * TILE_BYTES;
    static constexpr int SMEM = STG * STAGE_B;
};

template <int ABM>
__device__ __forceinline__ void load_chunk(
    uint32_t stage, const uint16_t* __restrict__ Ah, const uint16_t* __restrict__ Al,
    const uint16_t* __restrict__ Bh, const uint16_t* __restrict__ Bl,
    int m0, int n0, int kc, int K, int tid)
{
#pragma unroll
    for (int i = 0; i < 4; ++i) {
        int ch  = tid + i * 256;  // 0..1023
        int row = ch >> 3;
        int c16 = ch & 7;
        uint32_t soff = SWZ((uint32_t)(row * 128 + c16 * 16));
        size_t ga = ((size_t)(m0 + row) * K + (size_t)kc * 64) * 2 + (size_t)c16 * 16;
        size_t gb = ((size_t)(n0 + row) * K + (size_t)kc * 64) * 2 + (size_t)c16 * 16;
        if (ABM == 0) {
            CP_ASYNC16(stage + 0 * TILE_BYTES + soff, (const char*)Ah + ga);
            CP_ASYNC16(stage + 1 * TILE_BYTES + soff, (const char*)Al + ga);
            CP_ASYNC16(stage + 2 * TILE_BYTES + soff, (const char*)Bh + gb);
            CP_ASYNC16(stage + 3 * TILE_BYTES + soff, (const char*)Bl + gb);
        } else {
            CP_ASYNC16(stage + 0 * TILE_BYTES + soff, (const char*)Ah + ga);
            CP_ASYNC16(stage + 1 * TILE_BYTES + soff, (const char*)Bh + gb);
        }
    }
}

template <int ABM, int OUTM>
__global__ void __launch_bounds__(256, 1) gemm_kernel(
    const uint16_t* __restrict__ Ah, const uint16_t* __restrict__ Al,
    const uint16_t* __restrict__ Bh, const uint16_t* __restrict__ Bl,
    float* __restrict__ C, __nv_bfloat16* __restrict__ Chi,
    __nv_bfloat16* __restrict__ Clo, int M, int N, int K,
    const float* __restrict__ bias)
{
    constexpr int STG = Cfg<ABM>::STG;
    constexpr int STAGE_B = Cfg<ABM>::STAGE_B;

    extern __shared__ __align__(1024) unsigned char smem[];
    uint32_t sbase = smem_u32(smem);
    int tid = threadIdx.x, wid = tid >> 5, lane = tid & 31;
    int warp_m = wid & 1;   // 2 warps over M -> 64 rows
    int warp_n = wid >> 1;  // 4 warps over N -> 32 cols
    int m0 = blockIdx.y * 128, n0 = blockIdx.x * 128;

    float acc[4][4][4];
#pragma unroll
    for (int i = 0; i < 4; ++i)
#pragma unroll
        for (int j = 0; j < 4; ++j)
#pragma unroll
            for (int e = 0; e < 4; ++e) acc[i][j][e] = 0.0f;

    const int nch = K >> 6;

#pragma unroll
    for (int s = 0; s < STG - 1; ++s) {
        if (s < nch)
            load_chunk<ABM>(sbase + s * STAGE_B, Ah, Al, Bh, Bl, m0, n0, s, K, tid);
        CP_COMMIT();
    }

    const int a_rowbase = warp_m * 64 + (lane & 15);
    const int a_colb    = (lane >> 4) * 16;
    const int b_rowbase = warp_n * 32 + (lane & 7) + ((lane >> 3) & 1) * 8;
    const int b_colb    = (lane >> 4) * 16;

    for (int c = 0; c < nch; ++c) {
        if constexpr (STG == 3)      asm volatile("cp.async.wait_group 1;" ::: "memory");
        else if constexpr (STG == 6) asm volatile("cp.async.wait_group 4;" ::: "memory");
        else                         asm volatile("cp.async.wait_group 2;" ::: "memory");
        __syncthreads();

        int nextc = c + STG - 1;
        if (nextc < nch)
            load_chunk<ABM>(sbase + (uint32_t)(nextc % STG) * STAGE_B,
                            Ah, Al, Bh, Bl, m0, n0, nextc, K, tid);
        CP_COMMIT();

        uint32_t st = sbase + (uint32_t)(c % STG) * STAGE_B;

#pragma unroll
        for (int ks = 0; ks < 4; ++ks) {
            if (ABM == 0) {
                uint32_t tAh = st, tAl = st + TILE_BYTES;
                uint32_t tBh = st + 2 * TILE_BYTES, tBl = st + 3 * TILE_BYTES;
                uint32_t ah[4][4], al[4][4];
#pragma unroll
                for (int i = 0; i < 4; ++i) {
                    uint32_t off = SWZ((uint32_t)((a_rowbase + i * 16) * 128 + ks * 32 + a_colb));
                    ldmx4(ah[i], tAh + off);
                    ldmx4(al[i], tAl + off);
                }
                uint32_t bh[4][2], bl[4][2];
#pragma unroll
                for (int jb = 0; jb < 2; ++jb) {
                    uint32_t off = SWZ((uint32_t)((b_rowbase + jb * 16) * 128 + ks * 32 + b_colb));
                    uint32_t r[4];
                    ldmx4(r, tBh + off);
                    bh[jb * 2 + 0][0] = r[0]; bh[jb * 2 + 0][1] = r[2];
                    bh[jb * 2 + 1][0] = r[1]; bh[jb * 2 + 1][1] = r[3];
                    ldmx4(r, tBl + off);
                    bl[jb * 2 + 0][0] = r[0]; bl[jb * 2 + 0][1] = r[2];
                    bl[jb * 2 + 1][0] = r[1]; bl[jb * 2 + 1][1] = r[3];
                }
                // Three passes; each pass touches 16 DISTINCT accumulators, so
                // consecutive MMA issues are independent (no RAW chains). Per
                // accumulator the order is still hh -> hl -> lh (same numerics).
#pragma unroll
                for (int i = 0; i < 4; ++i)
#pragma unroll
                    for (int j = 0; j < 4; ++j)
                        mma_bf16(acc[i][j], ah[i], bh[j][0], bh[j][1]);  // hh
#pragma unroll
                for (int i = 0; i < 4; ++i)
#pragma unroll
                    for (int j = 0; j < 4; ++j)
                        mma_bf16(acc[i][j], ah[i], bl[j][0], bl[j][1]);  // hl
#pragma unroll
                for (int i = 0; i < 4; ++i)
#pragma unroll
                    for (int j = 0; j < 4; ++j)
                        mma_bf16(acc[i][j], al[i], bh[j][0], bh[j][1]);  // lh
            } else {
                uint32_t tAh = st;
                uint32_t tBh = st + TILE_BYTES;
                uint32_t ah[4][4];
#pragma unroll
                for (int i = 0; i < 4; ++i) {
                    uint32_t off = SWZ((uint32_t)((a_rowbase + i * 16) * 128 + ks * 32 + a_colb));
                    ldmx4(ah[i], tAh + off);
                }
                uint32_t bh[4][2];
#pragma unroll
                for (int jb = 0; jb < 2; ++jb) {
                    uint32_t off = SWZ((uint32_t)((b_rowbase + jb * 16) * 128 + ks * 32 + b_colb));
                    uint32_t r[4];
                    ldmx4(r, tBh + off);
                    bh[jb * 2 + 0][0] = r[0]; bh[jb * 2 + 0][1] = r[2];
                    bh[jb * 2 + 1][0] = r[1]; bh[jb * 2 + 1][1] = r[3];
                }
#pragma unroll
                for (int i = 0; i < 4; ++i)
#pragma unroll
                    for (int j = 0; j < 4; ++j)
                        mma_f16(acc[i][j], ah[i], bh[j][0], bh[j][1]);
            }
        }
        __syncthreads();
    }

    // Epilogue
    int g = lane >> 2, t = lane & 3;
#pragma unroll
    for (int i = 0; i < 4; ++i) {
        int r0 = m0 + warp_m * 64 + i * 16 + g;
#pragma unroll
        for (int j = 0; j < 4; ++j) {
            int col = n0 + warp_n * 32 + j * 8 + t * 2;
            float b0 = 0.0f, b1 = 0.0f;
            if (bias) { b0 = __ldg(bias + col); b1 = __ldg(bias + col + 1); }
            float v0 = acc[i][j][0] + b0, v1 = acc[i][j][1] + b1;
            float v2 = acc[i][j][2] + b0, v3 = acc[i][j][3] + b1;
            if (OUTM == 0) {
                *(float2*)(C + (size_t)r0 * N + col)       = make_float2(v0, v1);
                *(float2*)(C + (size_t)(r0 + 8) * N + col) = make_float2(v2, v3);
            } else {
                __nv_bfloat16 h0 = __float2bfloat16(v0), h1 = __float2bfloat16(v1);
                __nv_bfloat16 h2 = __float2bfloat16(v2), h3 = __float2bfloat16(v3);
                __nv_bfloat16 l0 = __float2bfloat16(v0 - __bfloat162float(h0));
                __nv_bfloat16 l1 = __float2bfloat16(v1 - __bfloat162float(h1));
                __nv_bfloat16 l2 = __float2bfloat16(v2 - __bfloat162float(h2));
                __nv_bfloat16 l3 = __float2bfloat16(v3 - __bfloat162float(h3));
                __nv_bfloat162 hh0; hh0.x = h0; hh0.y = h1;
                __nv_bfloat162 hh1; hh1.x = h2; hh1.y = h3;
                __nv_bfloat162 ll0; ll0.x = l0; ll0.y = l1;
                __nv_bfloat162 ll1; ll1.x = l2; ll1.y = l3;
                *(__nv_bfloat162*)(Chi + (size_t)r0 * N + col)       = hh0;
                *(__nv_bfloat162*)(Chi + (size_t)(r0 + 8) * N + col) = hh1;
                *(__nv_bfloat162*)(Clo + (size_t)r0 * N + col)       = ll0;
                *(__nv_bfloat162*)(Clo + (size_t)(r0 + 8) * N + col) = ll1;
            }
        }
    }
}

// ---------------------------------------------------------------------------
// fp32 -> (bf16 hi, bf16 lo) split
// ---------------------------------------------------------------------------
__global__ void split_kernel(const float* __restrict__ in,
                             __nv_bfloat16* __restrict__ hi,
                             __nv_bfloat16* __restrict__ lo, long long n)
{
    long long i = (long long)blockIdx.x * blockDim.x + threadIdx.x;
    long long stride = (long long)gridDim.x * blockDim.x;
    for (; i < n; i += stride) {
        float x = in[i];
        __nv_bfloat16 h = __float2bfloat16(x);
        hi[i] = h;
        lo[i] = __float2bfloat16(x - __bfloat162float(h));
    }
}

// ---------------------------------------------------------------------------
// Row softmax (N<=8192) writing fp16 probabilities
// ---------------------------------------------------------------------------
__global__ void __launch_bounds__(256) softmax_kernel(
    const float* __restrict__ S, __half* __restrict__ P, int N)
{
    __shared__ float buf[8192];
    __shared__ float red[8];
    int row = blockIdx.x, tid = threadIdx.x;
    const float* s = S + (long long)row * N;

    float mx = -3.0e38f;
    for (int i = tid; i < N; i += 256) mx = fmaxf(mx, s[i]);
#pragma unroll
    for (int o = 16; o; o >>= 1) mx = fmaxf(mx, __shfl_xor_sync(0xFFFFFFFFu, mx, o));
    if ((tid & 31) == 0) red[tid >> 5] = mx;
    __syncthreads();
    mx = red[0];
#pragma unroll
    for (int w = 1; w < 8; ++w) mx = fmaxf(mx, red[w]);

    float sum = 0.0f;
    for (int i = tid; i < N; i += 256) {
        float e = __expf(s[i] - mx);
        buf[i] = e;
        sum += e;
    }
#pragma unroll
    for (int o = 16; o; o >>= 1) sum += __shfl_xor_sync(0xFFFFFFFFu, sum, o);
    __syncthreads();
    if ((tid & 31) == 0) red[tid >> 5] = sum;
    __syncthreads();
    sum = 0.0f;
#pragma unroll
    for (int w = 0; w < 8; ++w) sum += red[w];
    float inv = 1.0f / sum;

    for (int i = tid; i < N; i += 256)
        P[(long long)row * N + i] = __float2half(buf[i] * inv);
}

// ---------------------------------------------------------------------------
// Transpose fp32 [R,C] -> fp16 [C,R]
// ---------------------------------------------------------------------------
__global__ void transpose_f16_kernel(const float* __restrict__ in,
                                     __half* __restrict__ thi, int R, int C)
{
    __shared__ float t[32][33];
    int c0 = blockIdx.x * 32, r0 = blockIdx.y * 32;
    int tx = threadIdx.x, ty = threadIdx.y;  // 32 x 8
#pragma unroll
    for (int j = 0; j < 4; ++j)
        t[ty + 8 * j][tx] = in[(long long)(r0 + ty + 8 * j) * C + c0 + tx];
    __syncthreads();
#pragma unroll
    for (int j = 0; j < 4; ++j) {
        float v = t[tx][ty + 8 * j];  // in[r0+tx][c0+ty+8j]
        long long o = (long long)(c0 + ty + 8 * j) * R + r0 + tx;
        thi[o] = __float2half(v);
    }
}

// ---------------------------------------------------------------------------
// Scratch
// ---------------------------------------------------------------------------
static constexpr size_t SZ_AX = (size_t)8192 * 1024;
static constexpr size_t SZ_W  = (size_t)512 * 1024;
static constexpr size_t SZ_QK = (size_t)8192 * 512;
static constexpr size_t SZ_S  = (size_t)8192 * 8192;

static constexpr size_t OFF_AHI  = 0;
static constexpr size_t OFF_ALO  = OFF_AHI  + SZ_AX * 2;
static constexpr size_t OFF_XHI  = OFF_ALO  + SZ_AX * 2;
static constexpr size_t OFF_XLO  = OFF_XHI  + SZ_AX * 2;
static constexpr size_t OFF_WQHI = OFF_XLO  + SZ_AX * 2;
static constexpr size_t OFF_WQLO = OFF_WQHI + SZ_W * 2;
static constexpr size_t OFF_WKHI = OFF_WQLO + SZ_W * 2;
static constexpr size_t OFF_WKLO = OFF_WKHI + SZ_W * 2;
static constexpr size_t OFF_QHI  = OFF_WKLO + SZ_W * 2;
static constexpr size_t OFF_QLO  = OFF_QHI  + SZ_QK * 2;
static constexpr size_t OFF_KHI  = OFF_QLO  + SZ_QK * 2;
static constexpr size_t OFF_KLO  = OFF_KHI  + SZ_QK * 2;
static constexpr size_t OFF_S    = OFF_KLO  + SZ_QK * 2;
static constexpr size_t OFF_PHI  = OFF_S    + SZ_S * 4;
static constexpr size_t OFF_XTHI = OFF_PHI  + SZ_S * 2;
static constexpr size_t SCRATCH_TOTAL = OFF_XTHI + SZ_AX * 2;

__device__ __align__(256) unsigned char g_scratch[SCRATCH_TOTAL];

// ---------------------------------------------------------------------------
// kernel_launch
// ---------------------------------------------------------------------------
extern "C" void kernel_launch(void* const* d_in, const int* in_sizes, int n_in,
                              void* d_out, int out_size)
{
    const float* A  = (const float*)d_in[0];
    const float* X  = (const float*)d_in[1];
    const float* Wq = (const float*)d_in[2];
    const float* bq = (const float*)d_in[3];
    const float* Wk = (const float*)d_in[4];
    const float* bk = (const float*)d_in[5];
    float* out = (float*)d_out;

    unsigned char* s = nullptr;
    cudaGetSymbolAddress((void**)&s, g_scratch);
    auto BF = [&](size_t off) { return (__nv_bfloat16*)(s + off); };
    auto U16 = [&](size_t off) { return (const uint16_t*)(s + off); };
    auto F  = [&](size_t off) { return (float*)(s + off); };

    cudaFuncSetAttribute(gemm_kernel<0, 0>,
                         cudaFuncAttributeMaxDynamicSharedMemorySize, Cfg<0>::SMEM);
    cudaFuncSetAttribute(gemm_kernel<0, 1>,
                         cudaFuncAttributeMaxDynamicSharedMemorySize, Cfg<0>::SMEM);
    cudaFuncSetAttribute(gemm_kernel<2, 0>,
                         cudaFuncAttributeMaxDynamicSharedMemorySize, Cfg<2>::SMEM);

    // Split inputs into bf16 hi/lo
    split_kernel<<<2048, 256>>>(A,  BF(OFF_AHI),  BF(OFF_ALO),  (long long)SZ_AX);
    split_kernel<<<2048, 256>>>(X,  BF(OFF_XHI),  BF(OFF_XLO),  (long long)SZ_AX);
    split_kernel<<<512,  256>>>(Wq, BF(OFF_WQHI), BF(OFF_WQLO), (long long)SZ_W);
    split_kernel<<<512,  256>>>(Wk, BF(OFF_WKHI), BF(OFF_WKLO), (long long)SZ_W);

    // Q/K GEMMs with fused split-bf16 epilogue (M=8192, N=512, K=1024)
    dim3 gq(512 / 128, 8192 / 128);
    gemm_kernel<0, 1><<<gq, 256, Cfg<0>::SMEM>>>(
        U16(OFF_AHI), U16(OFF_ALO), U16(OFF_WQHI), U16(OFF_WQLO),
        nullptr, BF(OFF_QHI), BF(OFF_QLO), 8192, 512, 1024, bq);
    gemm_kernel<0, 1><<<gq, 256, Cfg<0>::SMEM>>>(
        U16(OFF_XHI), U16(OFF_XLO), U16(OFF_WKHI), U16(OFF_WKLO),
        nullptr, BF(OFF_KHI), BF(OFF_KLO), 8192, 512, 1024, bk);

    // S = Q @ K^T   (M=8192, N=8192, K=512)
    dim3 gs(8192 / 128, 8192 / 128);
    gemm_kernel<0, 0><<<gs, 256, Cfg<0>::SMEM>>>(
        U16(OFF_QHI), U16(OFF_QLO), U16(OFF_KHI), U16(OFF_KLO),
        F(OFF_S), nullptr, nullptr, 8192, 8192, 512, nullptr);

    // P = softmax(S) -> fp16
    softmax_kernel<<<8192, 256>>>(F(OFF_S), (__half*)(s + OFF_PHI), 8192);

    // X^T -> fp16, K-major [1024, 8192]
    transpose_f16_kernel<<<dim3(1024 / 32, 8192 / 32), dim3(32, 8)>>>(
        X, (__half*)(s + OFF_XTHI), 8192, 1024);

    // O = P @ X   (M=8192, N=1024, K=8192), single fp16 MMA
    dim3 go(1024 / 128, 8192 / 128);
    gemm_kernel<2, 0><<<go, 256, Cfg<2>::SMEM>>>(
        U16(OFF_PHI), nullptr, U16(OFF_XTHI), nullptr,
        out, nullptr, nullptr, 8192, 1024, 8192, nullptr);
}